// round 1
// baseline (speedup 1.0000x reference)
#include <cuda_runtime.h>
#include <cuda_fp16.h>
#include <mma.h>

using namespace nvcuda;

#define BATCH 512
#define NTOK  256
#define DIN   256
#define TGT   256
#define TILE  64
#define LDA   264   // padded leading dim (halves) for smem activation buffers

// fp16 weight buffer offsets (elements)
#define GW0 0
#define GW1 65536
#define GW2 98304
#define GW3 131072
#define OW0 163840
#define OW1 196608
#define OW2 229376
#define OW3 262144
#define WTOT 294912

// smem: 4 activation buffers + fp32 epilogue scratch + mask/index arrays
#define SMEM_BYTES (4*TILE*LDA*2 + 8*256*4 + (TILE + TILE + 4)*4)

__device__ __half g_w16[WTOT];

__global__ void f2h_kernel(const float* __restrict__ src, int off, int n) {
    int i = blockIdx.x * blockDim.x + threadIdx.x;
    if (i < n) g_w16[off + i] = __float2half_rn(src[i]);
}

__global__ void zero_kernel(float* __restrict__ p, int n) {
    int i = blockIdx.x * blockDim.x + threadIdx.x;
    if (i < n) p[i] = 0.0f;
}

// One layer: dst[mrows x NOUT] = act( s1[mrows x K] @ W1 (+ s2 @ W2) + bias )
// s* in smem (row-major, ld=LDA, fp16). W* in gmem (row-major [K x NOUT], fp16).
// act: 0 = none, 1 = relu, 2 = sigmoid. 8 warps: warp -> (row-tile, col-half).
template<int K, int NOUT, bool DUAL>
__device__ __forceinline__ void gemm_layer(
    const __half* __restrict__ s1, const __half* __restrict__ W1,
    const __half* __restrict__ s2, const __half* __restrict__ W2,
    const float* __restrict__ bias, __half* __restrict__ dst,
    int mrows, int act, float* __restrict__ scratch)
{
    const int warp = threadIdx.x >> 5;
    const int lane = threadIdx.x & 31;
    const int rt   = warp >> 1;   // row tile 0..3 (16 rows each)
    const int ch   = warp & 1;    // column half
    constexpr int CT = NOUT / 32; // col tiles per warp (4 or 8)
    if (rt * 16 >= mrows) return;

    wmma::fragment<wmma::accumulator, 16, 16, 16, float> acc[CT];
    #pragma unroll
    for (int c = 0; c < CT; c++) wmma::fill_fragment(acc[c], 0.0f);

    #pragma unroll 4
    for (int kt = 0; kt < K / 16; kt++) {
        wmma::fragment<wmma::matrix_a, 16, 16, 16, __half, wmma::row_major> af;
        wmma::load_matrix_sync(af, s1 + (rt * 16) * LDA + kt * 16, LDA);
        #pragma unroll
        for (int c = 0; c < CT; c++) {
            wmma::fragment<wmma::matrix_b, 16, 16, 16, __half, wmma::row_major> bf;
            wmma::load_matrix_sync(bf, W1 + (kt * 16) * NOUT + (ch * CT + c) * 16, NOUT);
            wmma::mma_sync(acc[c], af, bf, acc[c]);
        }
    }
    if (DUAL) {
        #pragma unroll 4
        for (int kt = 0; kt < K / 16; kt++) {
            wmma::fragment<wmma::matrix_a, 16, 16, 16, __half, wmma::row_major> af;
            wmma::load_matrix_sync(af, s2 + (rt * 16) * LDA + kt * 16, LDA);
            #pragma unroll
            for (int c = 0; c < CT; c++) {
                wmma::fragment<wmma::matrix_b, 16, 16, 16, __half, wmma::row_major> bf;
                wmma::load_matrix_sync(bf, W2 + (kt * 16) * NOUT + (ch * CT + c) * 16, NOUT);
                wmma::mma_sync(acc[c], af, bf, acc[c]);
            }
        }
    }

    float* sw = scratch + warp * 256;
    #pragma unroll
    for (int c = 0; c < CT; c++) {
        wmma::store_matrix_sync(sw, acc[c], 16, wmma::mem_row_major);
        __syncwarp();
        const int c0 = (ch * CT + c) * 16;
        #pragma unroll
        for (int e = 0; e < 8; e++) {
            int idx = lane + e * 32;
            int r = idx >> 4, cc = idx & 15;
            float v = sw[idx] + bias[c0 + cc];
            if (act == 1)      v = fmaxf(v, 0.0f);
            else if (act == 2) v = 1.0f / (1.0f + __expf(-v));
            dst[(rt * 16 + r) * LDA + c0 + cc] = __float2half_rn(v);
        }
        __syncwarp();
    }
}

__global__ void __launch_bounds__(256, 1) readout_kernel(
    const float* __restrict__ h0, const float* __restrict__ hT,
    const float* __restrict__ gb0, const float* __restrict__ gb1,
    const float* __restrict__ gb2, const float* __restrict__ gb3,
    const float* __restrict__ ob0, const float* __restrict__ ob1,
    const float* __restrict__ ob2, const float* __restrict__ ob3,
    float* __restrict__ out)
{
    extern __shared__ char smem_raw[];
    __half* sA  = (__half*)smem_raw;        // h0 tile -> gate output
    __half* sHT = sA  + TILE * LDA;         // hT tile (persistent)
    __half* sB  = sHT + TILE * LDA;         // ping
    __half* sC  = sB  + TILE * LDA;         // pong / val output
    float*  scratch = (float*)(sC + TILE * LDA);
    int*    sMask   = (int*)(scratch + 8 * 256);
    int*    sIdx    = sMask + TILE;
    int*    sMp     = sIdx + TILE;

    const int warp = threadIdx.x >> 5;
    const int lane = threadIdx.x & 31;
    const int b    = blockIdx.y;
    const int n0   = blockIdx.x * TILE;
    const size_t base = ((size_t)b * NTOK + n0) * DIN;

    // 1) fp32 row sums of h0 -> validity mask (must be fp32: sign near zero)
    for (int rr = 0; rr < 8; ++rr) {
        int r = warp * 8 + rr;
        const float* p = h0 + base + (size_t)r * DIN;
        float s = 0.0f;
        #pragma unroll
        for (int c = lane; c < DIN; c += 32) s += p[c];
        #pragma unroll
        for (int o = 16; o > 0; o >>= 1) s += __shfl_down_sync(0xffffffffu, s, o);
        if (lane == 0) sMask[r] = (s > 0.0f) ? 1 : 0;
    }
    __syncthreads();
    if (threadIdx.x == 0) {
        int m = 0;
        for (int r = 0; r < TILE; r++) if (sMask[r]) sIdx[m++] = r;
        *sMp = m;
    }
    __syncthreads();
    const int m = *sMp;
    if (m == 0) return;                    // block-uniform
    const int mrows = (m + 15) & ~15;

    // 2) load compacted active rows (fp32 -> fp16), zero-pad to mrows
    for (int j = warp; j < TILE; j += 8) {
        if (j < m) {
            const int sr = sIdx[j];
            const float4* p0 = (const float4*)(h0 + base + (size_t)sr * DIN);
            const float4* p1 = (const float4*)(hT + base + (size_t)sr * DIN);
            #pragma unroll
            for (int q = 0; q < 2; q++) {
                float4 v0 = p0[lane + q * 32];
                float4 v1 = p1[lane + q * 32];
                int c0 = (lane + q * 32) * 4;
                sA [j * LDA + c0 + 0] = __float2half_rn(v0.x);
                sA [j * LDA + c0 + 1] = __float2half_rn(v0.y);
                sA [j * LDA + c0 + 2] = __float2half_rn(v0.z);
                sA [j * LDA + c0 + 3] = __float2half_rn(v0.w);
                sHT[j * LDA + c0 + 0] = __float2half_rn(v1.x);
                sHT[j * LDA + c0 + 1] = __float2half_rn(v1.y);
                sHT[j * LDA + c0 + 2] = __float2half_rn(v1.z);
                sHT[j * LDA + c0 + 3] = __float2half_rn(v1.w);
            }
        } else if (j < mrows) {
            #pragma unroll
            for (int q = 0; q < 2; q++) {
                int c0 = (lane + q * 32) * 4;
                #pragma unroll
                for (int u = 0; u < 4; u++) {
                    sA [j * LDA + c0 + u] = __half(0);
                    sHT[j * LDA + c0 + u] = __half(0);
                }
            }
        }
    }
    __syncthreads();

    // 3) gate MLP: concat(h0,hT) 512 -> 128 -> 256 -> 128 -> 256, sigmoid at end
    gemm_layer<256, 128, true >(sA,  g_w16 + GW0, sHT, g_w16 + GW0 + 256 * 128,
                                gb0, sB, mrows, 1, scratch);
    __syncthreads();
    gemm_layer<128, 256, false>(sB, g_w16 + GW1, nullptr, nullptr, gb1, sC, mrows, 1, scratch);
    __syncthreads();
    gemm_layer<256, 128, false>(sC, g_w16 + GW2, nullptr, nullptr, gb2, sB, mrows, 1, scratch);
    __syncthreads();
    gemm_layer<128, 256, false>(sB, g_w16 + GW3, nullptr, nullptr, gb3, sA, mrows, 2, scratch);
    __syncthreads();

    // 4) value MLP: hT 256 -> 128 -> 256 -> 128 -> 256 (linear output)
    gemm_layer<256, 128, false>(sHT, g_w16 + OW0, nullptr, nullptr, ob0, sB, mrows, 1, scratch);
    __syncthreads();
    gemm_layer<128, 256, false>(sB, g_w16 + OW1, nullptr, nullptr, ob1, sC, mrows, 1, scratch);
    __syncthreads();
    gemm_layer<256, 128, false>(sC, g_w16 + OW2, nullptr, nullptr, ob2, sB, mrows, 1, scratch);
    __syncthreads();
    gemm_layer<128, 256, false>(sB, g_w16 + OW3, nullptr, nullptr, ob3, sC, mrows, 0, scratch);
    __syncthreads();

    // 5) masked token reduction: out[b, t] += sum_j gate[j,t] * val[j,t]
    const int t = threadIdx.x;
    float s = 0.0f;
    for (int j = 0; j < m; ++j)
        s += __half2float(sA[j * LDA + t]) * __half2float(sC[j * LDA + t]);
    atomicAdd(out + (size_t)b * TGT + t, s);
}

extern "C" void kernel_launch(void* const* d_in, const int* in_sizes, int n_in,
                              void* d_out, int out_size)
{
    const float* h0 = (const float*)d_in[0];
    const float* hT = (const float*)d_in[1];
    const float* W[8]  = { (const float*)d_in[2],  (const float*)d_in[4],
                           (const float*)d_in[6],  (const float*)d_in[8],
                           (const float*)d_in[10], (const float*)d_in[12],
                           (const float*)d_in[14], (const float*)d_in[16] };
    const float* bs[8] = { (const float*)d_in[3],  (const float*)d_in[5],
                           (const float*)d_in[7],  (const float*)d_in[9],
                           (const float*)d_in[11], (const float*)d_in[13],
                           (const float*)d_in[15], (const float*)d_in[17] };
    float* out = (float*)d_out;

    const int offs[8] = { GW0, GW1, GW2, GW3, OW0, OW1, OW2, OW3 };
    const int sz[8]   = { 512 * 128, 128 * 256, 256 * 128, 128 * 256,
                          256 * 128, 128 * 256, 256 * 128, 128 * 256 };
    for (int i = 0; i < 8; i++)
        f2h_kernel<<<(sz[i] + 255) / 256, 256>>>(W[i], offs[i], sz[i]);

    zero_kernel<<<(out_size + 255) / 256, 256>>>(out, out_size);

    cudaFuncSetAttribute(readout_kernel,
                         cudaFuncAttributeMaxDynamicSharedMemorySize, SMEM_BYTES);
    dim3 grid(NTOK / TILE, BATCH);
    readout_kernel<<<grid, 256, SMEM_BYTES>>>(
        h0, hT, bs[0], bs[1], bs[2], bs[3], bs[4], bs[5], bs[6], bs[7], out);
}